// round 13
// baseline (speedup 1.0000x reference)
#include <cuda_runtime.h>
#include <cuda_bf16.h>

#define OUT_W    256
#define IMG_W    512
#define NBLK     512            // (ii in 256) x (i-half h in 2)
#define SK_T     16             // K rows per block
#define SK_W     388            // bf16x2 words per K row; 1552B = 16 mod 128
#define SREV_W   522            // padded reversed-row length in u32 words
#define OFF_K     0
#define OFF_SREV  24832         // 16*388*4
#define OFF_SREVB 26920         // + 522*4
#define SMEM_BYTES 29008        // + 522*4

#define NCHUNK   256            // one chunk per ii

__device__ float g_part[NCHUNK * 32 * OUT_W];   // 8 MB partials [ii][i][j]
__device__ float g_red[16 * 32 * OUT_W];        // 512 KB stage-A [grp][i][j]

__device__ __forceinline__ float frcp(float x) {
    float r; asm("rcp.approx.f32 %0, %1;" : "=f"(r) : "f"(x)); return r;
}
__device__ __forceinline__ void mma_bf16(float* d, unsigned a0, unsigned a1,
                                         unsigned a2, unsigned a3,
                                         unsigned b0, unsigned b1) {
    asm volatile(
        "mma.sync.aligned.m16n8k16.row.col.f32.bf16.bf16.f32 "
        "{%0,%1,%2,%3}, {%4,%5,%6,%7}, {%8,%9}, {%0,%1,%2,%3};"
        : "+f"(d[0]), "+f"(d[1]), "+f"(d[2]), "+f"(d[3])
        : "r"(a0), "r"(a1), "r"(a2), "r"(a3), "r"(b0), "r"(b1));
}

// ---------------------------------------------------------------------------
// Block (ii, h): one image row ii, i in [16h,16h+16). 8 warps = (wj: j-strip
// [64wj,64wj+64), 4 m-tiles x 2 n-tiles) x (se: e-half, 18 k-steps).
// Mainloop: per iteration TWO independent far-apart k-steps (q, q+9), each
// with a fresh 9-word Toeplitz A window + 4 B words -> MMAs of one step
// overlap the LDS of the other with no register shuffling.
// se-halves merged in-block via SMEM -> 256 partial chunks.
// ---------------------------------------------------------------------------
__global__ void __launch_bounds__(256, 4)
conv_mma_kernel(const float* __restrict__ img, const float* __restrict__ pos) {
    extern __shared__ char smem[];
    unsigned*      skw = (unsigned*)(smem + OFF_K);
    __nv_bfloat16* sr  = (__nv_bfloat16*)(smem + OFF_SREV);   // reversed row
    __nv_bfloat16* srB = (__nv_bfloat16*)(smem + OFF_SREVB);  // shifted +1

    const int ii  = blockIdx.x >> 1;
    const int h   = blockIdx.x & 1;
    const int tid = threadIdx.x;
    const float p0 = pos[0], p1 = pos[1];

    // ---- stage reversed image row (bf16): sr[z] = img[ii][767-z], z in [256,767]
    for (int z = tid; z < 2 * SREV_W; z += 256) {
        float v0 = (z >= 256 && z <= 767) ? img[ii * IMG_W + (767 - z)] : 0.f;
        int z1 = z + 1;
        float v1 = (z1 >= 256 && z1 <= 767) ? img[ii * IMG_W + (767 - z1)] : 0.f;
        sr [z] = __float2bfloat16_rn(v0);
        srB[z] = __float2bfloat16_rn(v1);
    }
    // ---- K rows: row t serves i = 16h + t  (d-255 = 16h + t - ii)
    for (int t = 0; t < SK_T; t++) {
        float dx  = (float)(16 * h + t - ii) + p0;
        float dx2 = dx * dx;
        for (int u = tid; u < SK_W; u += 256) {
            float dy0 = (float)(2 * u - 511) + p1;
            float dy1 = dy0 + 1.0f;
            float v0 = (2 * u     < 767) ? frcp(fmaf(dy0, dy0, dx2)) : 0.f;
            float v1 = (2 * u + 1 < 767) ? frcp(fmaf(dy1, dy1, dx2)) : 0.f;
            unsigned wv;
            asm("cvt.rn.bf16x2.f32 %0, %1, %2;" : "=r"(wv) : "f"(v1), "f"(v0));
            skw[t * SK_W + u] = wv;
        }
    }
    __syncthreads();

    const int w    = tid >> 5;
    const int wj   = w & 3;           // j strip [64wj, 64wj+64)
    const int se   = w >> 2;          // e-half: k-steps q in [18se, 18se+18)
    const int lane = tid & 31;
    const int r    = lane >> 2;
    const int c    = lane & 3;
    const int sel  = r & 1;

    const unsigned* pA = (const unsigned*)(sel ? srB : sr)
                         + ((2 * c - 64 * wj - r + 256 - sel) >> 1);
    const unsigned* pB = skw + r * SK_W + c;
    const int ew0 = 32 * wj + 8 * 18 * se;

    float acc[4][2][4];
#pragma unroll
    for (int m = 0; m < 4; m++)
#pragma unroll
        for (int n = 0; n < 2; n++)
#pragma unroll
            for (int k = 0; k < 4; k++) acc[m][n][k] = 0.f;

#define LOADW(W_, ew_)                                                        \
    { _Pragma("unroll")                                                       \
      for (int k = 0; k < 9; k++) W_[k] = pA[(ew_) + 4 - 4 * k]; }
#define LOADB(B_, ew_)                                                        \
    { B_[0] = pB[(ew_)];               B_[1] = pB[(ew_) + 4];                 \
      B_[2] = pB[8 * SK_W + (ew_)];    B_[3] = pB[8 * SK_W + (ew_) + 4]; }
#define MMAQ(W_, B_)                                                          \
    { _Pragma("unroll")                                                       \
      for (int m = 0; m < 4; m++) {                                           \
          mma_bf16(acc[m][0], W_[2*m+1], W_[2*m+2], W_[2*m], W_[2*m+1],       \
                   B_[0], B_[1]);                                             \
          mma_bf16(acc[m][1], W_[2*m+1], W_[2*m+2], W_[2*m], W_[2*m+1],       \
                   B_[2], B_[3]);                                             \
      } }

#pragma unroll 1
    for (int it = 0; it < 9; it++) {
        const int ewa = ew0 + 8 * it;         // step q = base + it
        const int ewb = ewa + 72;             // step q + 9 (independent)
        unsigned Wa[9], Wb[9], Ba[4], Bb[4];
        LOADW(Wa, ewa); LOADB(Ba, ewa);
        LOADW(Wb, ewb); LOADB(Bb, ewb);
        MMAQ(Wa, Ba);
        MMAQ(Wb, Bb);
    }
#undef LOADW
#undef LOADB
#undef MMAQ

    // ---- merge e-halves in-block (skw region is dead after this sync) ----
    float* mbuf = (float*)smem;       // [wj][32 idx][32 lanes] = 16 KB
    __syncthreads();
    if (se == 1) {
        float* bp = mbuf + wj * 1024 + lane;
#pragma unroll
        for (int m = 0; m < 4; m++)
#pragma unroll
            for (int n = 0; n < 2; n++)
#pragma unroll
                for (int k = 0; k < 4; k++)
                    bp[(((m * 2 + n) * 4) + k) * 32] = acc[m][n][k];
    }
    __syncthreads();
    if (se == 0) {
        const float* bp = mbuf + wj * 1024 + lane;
        float* dst = g_part + ii * (32 * OUT_W) + (16 * h) * OUT_W;
#pragma unroll
        for (int m = 0; m < 4; m++) {
            const int j0 = 64 * wj + 16 * m + r;
#pragma unroll
            for (int nn = 0; nn < 2; nn++) {
                const int il = 8 * nn + 2 * c;
                float v0 = acc[m][nn][0] + bp[(((m*2+nn)*4) + 0) * 32];
                float v1 = acc[m][nn][1] + bp[(((m*2+nn)*4) + 1) * 32];
                float v2 = acc[m][nn][2] + bp[(((m*2+nn)*4) + 2) * 32];
                float v3 = acc[m][nn][3] + bp[(((m*2+nn)*4) + 3) * 32];
                dst[(il    ) * OUT_W + j0    ] = v0;
                dst[(il + 1) * OUT_W + j0    ] = v1;
                dst[(il    ) * OUT_W + j0 + 8] = v2;
                dst[(il + 1) * OUT_W + j0 + 8] = v3;
            }
        }
    }
}

// ---------------------------------------------------------------------------
// Two-stage deterministic reduction over 256 chunks (R12-proven shape).
// ---------------------------------------------------------------------------
__global__ void reduce_a_kernel() {
    const int g  = blockIdx.x >> 5;                  // 16 groups of 16 chunks
    const int o  = (blockIdx.x & 31) * 256 + threadIdx.x;
    const int c0 = g * 16;
    float s0 = 0.f, s1 = 0.f, s2 = 0.f, s3 = 0.f;
#pragma unroll
    for (int c = 0; c < 16; c += 4) {
        s0 += g_part[(c0 + c + 0) * 8192 + o];
        s1 += g_part[(c0 + c + 1) * 8192 + o];
        s2 += g_part[(c0 + c + 2) * 8192 + o];
        s3 += g_part[(c0 + c + 3) * 8192 + o];
    }
    g_red[g * 8192 + o] = (s0 + s1) + (s2 + s3);
}

__global__ void reduce_b_kernel(float* __restrict__ out) {
    const int o = blockIdx.x * 256 + threadIdx.x;
    float s = 0.f;
#pragma unroll
    for (int g = 0; g < 16; g++) s += g_red[g * 8192 + o];
    out[o] = s;
}

// ---------------------------------------------------------------------------
extern "C" void kernel_launch(void* const* d_in, const int* in_sizes, int n_in,
                              void* d_out, int out_size) {
    const float* img = (const float*)d_in[0];   // [256, 512] f32
    const float* pos = (const float*)d_in[1];   // [2] f32
    float* out = (float*)d_out;                 // [32, 256] f32

    conv_mma_kernel<<<NBLK, 256, SMEM_BYTES>>>(img, pos);
    reduce_a_kernel<<<512, 256>>>();
    reduce_b_kernel<<<32, 256>>>(out);
}

// round 14
// speedup vs baseline: 1.0137x; 1.0137x over previous
#include <cuda_runtime.h>
#include <cuda_bf16.h>

#define OUT_W    256
#define IMG_W    512
#define NBLK     512            // (ii in 256) x (i-half h in 2)
#define SK_T     16             // K rows per block
#define SK_W     388            // bf16x2 words per K row; 1552B = 16 mod 128
#define SREV_W   522            // padded reversed-row length in u32 words
#define OFF_K     0
#define OFF_SREV  24832         // 16*388*4
#define OFF_SREVB 26920         // + 522*4
#define SMEM_BYTES 29008        // + 522*4

#define NCHUNK   256            // one chunk per ii

__device__ float g_part[NCHUNK * 32 * OUT_W];   // 8 MB partials [ii][i][j]
__device__ float g_red[16 * 32 * OUT_W];        // 512 KB stage-A [grp][i][j]

__device__ __forceinline__ float frcp(float x) {
    float r; asm("rcp.approx.f32 %0, %1;" : "=f"(r) : "f"(x)); return r;
}
__device__ __forceinline__ void mma_bf16(float* d, unsigned a0, unsigned a1,
                                         unsigned a2, unsigned a3,
                                         unsigned b0, unsigned b1) {
    asm volatile(
        "mma.sync.aligned.m16n8k16.row.col.f32.bf16.bf16.f32 "
        "{%0,%1,%2,%3}, {%4,%5,%6,%7}, {%8,%9}, {%0,%1,%2,%3};"
        : "+f"(d[0]), "+f"(d[1]), "+f"(d[2]), "+f"(d[3])
        : "r"(a0), "r"(a1), "r"(a2), "r"(a3), "r"(b0), "r"(b1));
}

// ---------------------------------------------------------------------------
// Block (ii, h): one image row ii, i in [16h,16h+16). 8 warps = (wj: j-strip
// [64wj,64wj+64), 4 m-tiles x 2 n-tiles) x (se: e-half, 18 k-steps).
// Mainloop is the R10-proven naive form: per k-step a fresh 9-word Toeplitz
// A window + 4 B words + 8 MMAs, no cross-step register structure — ptxas
// schedules the 13 independent LDS against the MMAs better than any hand
// pipeline (measured R10-R13). se-halves merged in-block -> 256 chunks.
// ---------------------------------------------------------------------------
__global__ void __launch_bounds__(256, 4)
conv_mma_kernel(const float* __restrict__ img, const float* __restrict__ pos) {
    extern __shared__ char smem[];
    unsigned*      skw = (unsigned*)(smem + OFF_K);
    __nv_bfloat16* sr  = (__nv_bfloat16*)(smem + OFF_SREV);   // reversed row
    __nv_bfloat16* srB = (__nv_bfloat16*)(smem + OFF_SREVB);  // shifted +1

    const int ii  = blockIdx.x >> 1;
    const int h   = blockIdx.x & 1;
    const int tid = threadIdx.x;
    const float p0 = pos[0], p1 = pos[1];

    // ---- stage reversed image row (bf16): sr[z] = img[ii][767-z], z in [256,767]
    for (int z = tid; z < 2 * SREV_W; z += 256) {
        float v0 = (z >= 256 && z <= 767) ? img[ii * IMG_W + (767 - z)] : 0.f;
        int z1 = z + 1;
        float v1 = (z1 >= 256 && z1 <= 767) ? img[ii * IMG_W + (767 - z1)] : 0.f;
        sr [z] = __float2bfloat16_rn(v0);
        srB[z] = __float2bfloat16_rn(v1);
    }
    // ---- K rows: row t serves i = 16h + t  (d-255 = 16h + t - ii)
    for (int t = 0; t < SK_T; t++) {
        float dx  = (float)(16 * h + t - ii) + p0;
        float dx2 = dx * dx;
        for (int u = tid; u < SK_W; u += 256) {
            float dy0 = (float)(2 * u - 511) + p1;
            float dy1 = dy0 + 1.0f;
            float v0 = (2 * u     < 767) ? frcp(fmaf(dy0, dy0, dx2)) : 0.f;
            float v1 = (2 * u + 1 < 767) ? frcp(fmaf(dy1, dy1, dx2)) : 0.f;
            unsigned wv;
            asm("cvt.rn.bf16x2.f32 %0, %1, %2;" : "=r"(wv) : "f"(v1), "f"(v0));
            skw[t * SK_W + u] = wv;
        }
    }
    __syncthreads();

    const int w    = tid >> 5;
    const int wj   = w & 3;           // j strip [64wj, 64wj+64)
    const int se   = w >> 2;          // e-half: k-steps q in [18se, 18se+18)
    const int lane = tid & 31;
    const int r    = lane >> 2;
    const int c    = lane & 3;
    const int sel  = r & 1;

    const unsigned* pA = (const unsigned*)(sel ? srB : sr)
                         + ((2 * c - 64 * wj - r + 256 - sel) >> 1);
    const unsigned* pB = skw + r * SK_W + c;

    float acc[4][2][4];
#pragma unroll
    for (int m = 0; m < 4; m++)
#pragma unroll
        for (int n = 0; n < 2; n++)
#pragma unroll
            for (int k = 0; k < 4; k++) acc[m][n][k] = 0.f;

    // k-steps q in [18se, 18se+18): e-words [32wj+8q, +8)  (R10-proven body)
#pragma unroll 1
    for (int q = 18 * se; q < 18 * se + 18; q++) {
        const int ew = 32 * wj + 8 * q;
        unsigned W[9];
#pragma unroll
        for (int k = 0; k < 9; k++) W[k] = pA[ew + 4 - 4 * k];
        unsigned b00 = pB[ew],            b01 = pB[ew + 4];
        unsigned b10 = pB[8 * SK_W + ew], b11 = pB[8 * SK_W + ew + 4];
#pragma unroll
        for (int m = 0; m < 4; m++) {
            mma_bf16(acc[m][0], W[2*m+1], W[2*m+2], W[2*m], W[2*m+1], b00, b01);
            mma_bf16(acc[m][1], W[2*m+1], W[2*m+2], W[2*m], W[2*m+1], b10, b11);
        }
    }

    // ---- merge e-halves in-block (skw region is dead after this sync) ----
    float* mbuf = (float*)smem;       // [wj][32 idx][32 lanes] = 16 KB
    __syncthreads();
    if (se == 1) {
        float* bp = mbuf + wj * 1024 + lane;
#pragma unroll
        for (int m = 0; m < 4; m++)
#pragma unroll
            for (int n = 0; n < 2; n++)
#pragma unroll
                for (int k = 0; k < 4; k++)
                    bp[(((m * 2 + n) * 4) + k) * 32] = acc[m][n][k];
    }
    __syncthreads();
    if (se == 0) {
        const float* bp = mbuf + wj * 1024 + lane;
        float* dst = g_part + ii * (32 * OUT_W) + (16 * h) * OUT_W;
#pragma unroll
        for (int m = 0; m < 4; m++) {
            const int j0 = 64 * wj + 16 * m + r;
#pragma unroll
            for (int nn = 0; nn < 2; nn++) {
                const int il = 8 * nn + 2 * c;
                float v0 = acc[m][nn][0] + bp[(((m*2+nn)*4) + 0) * 32];
                float v1 = acc[m][nn][1] + bp[(((m*2+nn)*4) + 1) * 32];
                float v2 = acc[m][nn][2] + bp[(((m*2+nn)*4) + 2) * 32];
                float v3 = acc[m][nn][3] + bp[(((m*2+nn)*4) + 3) * 32];
                dst[(il    ) * OUT_W + j0    ] = v0;
                dst[(il + 1) * OUT_W + j0    ] = v1;
                dst[(il    ) * OUT_W + j0 + 8] = v2;
                dst[(il + 1) * OUT_W + j0 + 8] = v3;
            }
        }
    }
}

// ---------------------------------------------------------------------------
// Two-stage deterministic reduction over 256 chunks (R12-proven shape).
// ---------------------------------------------------------------------------
__global__ void reduce_a_kernel() {
    const int g  = blockIdx.x >> 5;                  // 16 groups of 16 chunks
    const int o  = (blockIdx.x & 31) * 256 + threadIdx.x;
    const int c0 = g * 16;
    float s0 = 0.f, s1 = 0.f, s2 = 0.f, s3 = 0.f;
#pragma unroll
    for (int c = 0; c < 16; c += 4) {
        s0 += g_part[(c0 + c + 0) * 8192 + o];
        s1 += g_part[(c0 + c + 1) * 8192 + o];
        s2 += g_part[(c0 + c + 2) * 8192 + o];
        s3 += g_part[(c0 + c + 3) * 8192 + o];
    }
    g_red[g * 8192 + o] = (s0 + s1) + (s2 + s3);
}

__global__ void reduce_b_kernel(float* __restrict__ out) {
    const int o = blockIdx.x * 256 + threadIdx.x;
    float s = 0.f;
#pragma unroll
    for (int g = 0; g < 16; g++) s += g_red[g * 8192 + o];
    out[o] = s;
}

// ---------------------------------------------------------------------------
extern "C" void kernel_launch(void* const* d_in, const int* in_sizes, int n_in,
                              void* d_out, int out_size) {
    const float* img = (const float*)d_in[0];   // [256, 512] f32
    const float* pos = (const float*)d_in[1];   // [2] f32
    float* out = (float*)d_out;                 // [32, 256] f32

    conv_mma_kernel<<<NBLK, 256, SMEM_BYTES>>>(img, pos);
    reduce_a_kernel<<<512, 256>>>();
    reduce_b_kernel<<<32, 256>>>(out);
}